// round 16
// baseline (speedup 1.0000x reference)
#include <cuda_runtime.h>
#include <cuda_fp16.h>
#include <cstdint>

// Problem constants
#define N_ROWS   32768
#define D_DIM    512
#define C_BOOKS  64
#define K_CODES  16
#define M_OUT    128
#define NODES    15

// Scratch
__device__ __align__(16) uint32_t g_codes[N_ROWS * 8];               // 4-bit codes
__device__ __align__(16) __half   g_Lf16[M_OUT * C_BOOKS * K_CODES]; // L fp16 [m][1024]

// ---------------------------------------------------------------------------
// PTX helpers (sm_103 baseline — harness ptxas targets sm_103, no tcgen05)
// ---------------------------------------------------------------------------
__device__ __forceinline__ uint32_t smem_u32(const void* p) {
    uint32_t a;
    asm("{ .reg .u64 t; cvta.to.shared.u64 t, %1; cvt.u32.u64 %0, t; }" : "=r"(a) : "l"(p));
    return a;
}
__device__ __forceinline__ void cp16(uint32_t dst, const void* src) {
    asm volatile("cp.async.cg.shared.global [%0], [%1], 16;" :: "r"(dst), "l"(src) : "memory");
}
#define CP_COMMIT() asm volatile("cp.async.commit_group;" ::: "memory")
#define CP_WAIT(n)  asm volatile("cp.async.wait_group %0;" :: "n"(n) : "memory")

__device__ __forceinline__ void ldsm4(uint32_t& r0, uint32_t& r1, uint32_t& r2,
                                      uint32_t& r3, uint32_t addr) {
    asm volatile("ldmatrix.sync.aligned.m8n8.x4.shared.b16 {%0,%1,%2,%3}, [%4];"
                 : "=r"(r0), "=r"(r1), "=r"(r2), "=r"(r3) : "r"(addr));
}
// fp16-accumulate MMA: D (2 regs, half2 x2) = A*B + D, full-rate HMMA
__device__ __forceinline__ void mma16816_f16(uint32_t* c, uint32_t a0, uint32_t a1,
                                             uint32_t a2, uint32_t a3,
                                             uint32_t b0, uint32_t b1) {
    asm volatile("mma.sync.aligned.m16n8k16.row.col.f16.f16.f16.f16 "
                 "{%0,%1}, {%2,%3,%4,%5}, {%6,%7}, {%0,%1};"
                 : "+r"(c[0]), "+r"(c[1])
                 : "r"(a0), "r"(a1), "r"(a2), "r"(a3), "r"(b0), "r"(b1));
}

// ---------------------------------------------------------------------------
// Kernel 1: encode (16 rows/CTA, 256 threads) + fused L->fp16 convert.
// ---------------------------------------------------------------------------
#define ENC_ROWS    16
#define ENC_THREADS 256
#define ROW_PAD     516

__global__ __launch_bounds__(ENC_THREADS)
void encode_kernel(const float* __restrict__ I,
                   const float* __restrict__ T,
                   const int*   __restrict__ dims,
                   const float* __restrict__ L)
{
    extern __shared__ float sm[];
    float* Ir = sm;
    float* Ts = sm + ENC_ROWS * ROW_PAD;
    int*   ds = (int*)(Ts + 960);

    const int tid = threadIdx.x;
    const int nb  = blockIdx.x * ENC_ROWS;
    const uint32_t sbase = smem_u32(sm);

    const char* src = (const char*)(I + (size_t)nb * D_DIM);
    #pragma unroll
    for (int i = 0; i < 8; i++) {
        int q = tid + ENC_THREADS * i;
        int r = q >> 7;
        int j = q & 127;
        cp16(sbase + (uint32_t)(r * (ROW_PAD * 4) + j * 16),
             src + (size_t)r * (D_DIM * 4) + j * 16);
    }
    CP_COMMIT();

    if (blockIdx.x < 128) {
        int q = blockIdx.x * 256 + tid;
        float4 v = ((const float4*)L)[q];
        ((__half2*)g_Lf16)[q * 2]     = __floats2half2_rn(v.x, v.y);
        ((__half2*)g_Lf16)[q * 2 + 1] = __floats2half2_rn(v.z, v.w);
    }

    for (int i = tid; i < 960; i += ENC_THREADS) Ts[i] = T[i];
    ds[tid] = dims[tid];

    CP_WAIT(0);
    __syncthreads();

    const int r  = tid >> 4;
    const int cg = tid & 15;
    const float* row = Ir + r * ROW_PAD;

    uint32_t pack = 0;
    #pragma unroll
    for (int j = 0; j < 4; j++) {
        const int c = cg * 4 + j;
        const int*   dp = ds + c * 4;
        const float* tp = Ts + c * NODES;
        const float v0 = row[dp[0]];
        const float v1 = row[dp[1]];
        const float v2 = row[dp[2]];
        const float v3 = row[dp[3]];
        int p;
        p = (v0 > tp[0]) ? 1 : 0;
        p = (p << 1) | ((v1 > tp[1 + p]) ? 1 : 0);
        p = (p << 1) | ((v2 > tp[3 + p]) ? 1 : 0);
        p = (p << 1) | ((v3 > tp[7 + p]) ? 1 : 0);
        pack |= ((uint32_t)p) << (4 * j);
    }
    ((uint16_t*)g_codes)[(size_t)(nb + r) * 16 + cg] = (uint16_t)pack;
}

// ---------------------------------------------------------------------------
// Kernel 2: tensor aggregation, barrier-free (r14/r15 skeleton) with
// FP16-ACCUMULATE MMA (full-rate HMMA) + per-chunk fp32 flush:
// fp16 acc sees at most 8 adds (one 8-codebook chunk) before being folded
// into fp32 registers — bounds rounding error to ~2e-4 rel.
// CTA = 512n x 64m, 512 threads; warp = 32n x 64m; A via SMEM LUT; B staged
// as two ldsm pairs to cap live regs. Grid (64,2) = 128 CTAs = single wave.
// ---------------------------------------------------------------------------
#define AGG_THREADS 512
#define NTILE       512
#define MTILE       64
#define BROW        2064                         // 2048B data + 16B pad per m-row
#define SM_CODES    0                            // 512 rows * 32B = 16384
#define SM_LUT      16384                        // 64 x uint2 = 512
#define SM_B        17408                        // 1024-aligned
#define SM_AGG      (SM_B + MTILE * BROW)        // 149504

__global__ __launch_bounds__(AGG_THREADS)
void agg_kernel(float* __restrict__ out)
{
    extern __shared__ __align__(16) char smem[];
    const uint32_t sb = smem_u32(smem);
    const int tid  = threadIdx.x;
    const int wid  = tid >> 5;
    const int lane = tid & 31;
    const int g    = lane >> 2;     // 0..7
    const int tg   = lane & 3;      // 0..3
    const int n0   = blockIdx.x * NTILE;
    const int mg0  = blockIdx.y * MTILE;

    // ---- stage codes ----
    {
        const char* srcc = (const char*)(g_codes + (size_t)n0 * 8);
        #pragma unroll
        for (int i = 0; i < 2; i++) {
            int q = tid + AGG_THREADS * i;
            cp16(sb + SM_CODES + (uint32_t)(q * 16), srcc + (size_t)q * 16);
        }
    }
    // ---- stage B: 64 m-rows x 128 x 16B ----
    {
        const char* srcL = (const char*)g_Lf16 + (size_t)mg0 * 2048;
        #pragma unroll
        for (int i = 0; i < 16; i++) {
            int q = tid + AGG_THREADS * i;
            int m = q >> 7, seg = q & 127;
            cp16(sb + SM_B + (uint32_t)(m * BROW + seg * 16),
                 srcL + (size_t)m * 2048 + seg * 16);
        }
    }
    CP_COMMIT();

    // ---- A-fragment LUT: entry[k][t] = {A_klow_slot, A_khigh_slot} ----
    if (tid < 64) {
        const uint32_t k  = (uint32_t)(tid >> 2);
        const uint32_t tt = (uint32_t)(tid & 3);
        const uint32_t hv = 0x3C00u << ((k & 1u) << 4);
        const uint32_t s  = k >> 1;
        uint2 e;
        e.x = (s == tt)      ? hv : 0u;
        e.y = (s == tt + 4u) ? hv : 0u;
        ((uint2*)(smem + SM_LUT))[tid] = e;
    }

    CP_WAIT(0);
    __syncthreads();            // the ONLY barrier

    const int t = lane >> 3;
    const uint32_t lane_off = (uint32_t)((((t >> 1) * 8) + (lane & 7)) * BROW
                                         + (t & 1) * 16);

    const int rbase = wid * 32;
    const uint32_t* cs = (const uint32_t*)smem;
    const uint2* LUT = (const uint2*)(smem + SM_LUT);
    const uint32_t bwarp = sb + SM_B + lane_off;

    float acc[2][8][4];
    #pragma unroll
    for (int rt = 0; rt < 2; rt++)
        #pragma unroll
        for (int nb = 0; nb < 8; nb++)
            #pragma unroll
            for (int i = 0; i < 4; i++) acc[rt][nb][i] = 0.f;

    #pragma unroll 1
    for (int ch = 0; ch < 8; ch++) {
        const uint32_t bbase = bwarp + (uint32_t)(ch * 256);

        uint32_t wlo[2], whi[2];
        #pragma unroll
        for (int rt = 0; rt < 2; rt++) {
            wlo[rt] = cs[(rbase + 16 * rt + g)     * 8 + ch];
            whi[rt] = cs[(rbase + 16 * rt + g + 8) * 8 + ch];
        }

        // fp16 accumulators, zeroed each chunk (max 8 adds before flush)
        uint32_t acc16[2][8][2];
        #pragma unroll
        for (int rt = 0; rt < 2; rt++)
            #pragma unroll
            for (int nb = 0; nb < 8; nb++) {
                acc16[rt][nb][0] = 0u; acc16[rt][nb][1] = 0u;
            }

        #pragma unroll
        for (int kbl = 0; kbl < 8; kbl++) {
            const uint32_t bk = bbase + (uint32_t)(kbl * 32);

            uint2 elo[2], ehi[2];
            #pragma unroll
            for (int rt = 0; rt < 2; rt++) {
                const uint32_t klo = (wlo[rt] >> (4 * kbl)) & 15u;
                const uint32_t khi = (whi[rt] >> (4 * kbl)) & 15u;
                elo[rt] = LUT[(int)(klo * 4) + tg];
                ehi[rt] = LUT[(int)(khi * 4) + tg];
            }

            // First B pair (m 0..31)
            {
                uint32_t b[2][4];
                ldsm4(b[0][0], b[0][1], b[0][2], b[0][3], bk);
                ldsm4(b[1][0], b[1][1], b[1][2], b[1][3],
                      bk + (uint32_t)(16 * BROW));
                #pragma unroll
                for (int rt = 0; rt < 2; rt++) {
                    mma16816_f16(acc16[rt][0], elo[rt].x, ehi[rt].x,
                                 elo[rt].y, ehi[rt].y, b[0][0], b[0][1]);
                    mma16816_f16(acc16[rt][1], elo[rt].x, ehi[rt].x,
                                 elo[rt].y, ehi[rt].y, b[0][2], b[0][3]);
                    mma16816_f16(acc16[rt][2], elo[rt].x, ehi[rt].x,
                                 elo[rt].y, ehi[rt].y, b[1][0], b[1][1]);
                    mma16816_f16(acc16[rt][3], elo[rt].x, ehi[rt].x,
                                 elo[rt].y, ehi[rt].y, b[1][2], b[1][3]);
                }
            }
            // Second B pair (m 32..63)
            {
                uint32_t b[2][4];
                ldsm4(b[0][0], b[0][1], b[0][2], b[0][3],
                      bk + (uint32_t)(2 * 16 * BROW));
                ldsm4(b[1][0], b[1][1], b[1][2], b[1][3],
                      bk + (uint32_t)(3 * 16 * BROW));
                #pragma unroll
                for (int rt = 0; rt < 2; rt++) {
                    mma16816_f16(acc16[rt][4], elo[rt].x, ehi[rt].x,
                                 elo[rt].y, ehi[rt].y, b[0][0], b[0][1]);
                    mma16816_f16(acc16[rt][5], elo[rt].x, ehi[rt].x,
                                 elo[rt].y, ehi[rt].y, b[0][2], b[0][3]);
                    mma16816_f16(acc16[rt][6], elo[rt].x, ehi[rt].x,
                                 elo[rt].y, ehi[rt].y, b[1][0], b[1][1]);
                    mma16816_f16(acc16[rt][7], elo[rt].x, ehi[rt].x,
                                 elo[rt].y, ehi[rt].y, b[1][2], b[1][3]);
                }
            }
        }

        // Flush chunk's fp16 partials into fp32 accumulators
        #pragma unroll
        for (int rt = 0; rt < 2; rt++)
            #pragma unroll
            for (int nb = 0; nb < 8; nb++) {
                __half2 h0 = *(__half2*)&acc16[rt][nb][0];   // row g, cols 2tg..
                __half2 h1 = *(__half2*)&acc16[rt][nb][1];   // row g+8
                float2 f0 = __half22float2(h0);
                float2 f1 = __half22float2(h1);
                acc[rt][nb][0] += f0.x;
                acc[rt][nb][1] += f0.y;
                acc[rt][nb][2] += f1.x;
                acc[rt][nb][3] += f1.y;
            }
    }

    // Epilogue: STG.64 pairs
    #pragma unroll
    for (int rt = 0; rt < 2; rt++) {
        const int rowA = n0 + rbase + 16 * rt + g;
        #pragma unroll
        for (int nb = 0; nb < 8; nb++) {
            float2 lo = make_float2(acc[rt][nb][0], acc[rt][nb][1]);
            float2 hi = make_float2(acc[rt][nb][2], acc[rt][nb][3]);
            *(float2*)(out + (size_t)rowA * M_OUT + mg0 + nb * 8 + tg * 2)       = lo;
            *(float2*)(out + (size_t)(rowA + 8) * M_OUT + mg0 + nb * 8 + tg * 2) = hi;
        }
    }
}

// ---------------------------------------------------------------------------
extern "C" void kernel_launch(void* const* d_in, const int* in_sizes, int n_in,
                              void* d_out, int out_size)
{
    (void)in_sizes; (void)n_in; (void)out_size;
    const float* I    = (const float*)d_in[0];
    const float* T    = (const float*)d_in[1];
    const float* L    = (const float*)d_in[2];
    const int*   dims = (const int*)d_in[5];
    float* out = (float*)d_out;

    const int encSmem = (ENC_ROWS * ROW_PAD + 960 + 256) * 4;  // 37888
    cudaFuncSetAttribute(encode_kernel, cudaFuncAttributeMaxDynamicSharedMemorySize, encSmem);
    cudaFuncSetAttribute(agg_kernel,    cudaFuncAttributeMaxDynamicSharedMemorySize, SM_AGG);

    encode_kernel<<<N_ROWS / ENC_ROWS, ENC_THREADS, encSmem>>>(I, T, dims, L);
    agg_kernel<<<dim3(N_ROWS / NTILE, M_OUT / MTILE), AGG_THREADS, SM_AGG>>>(out);
}

// round 17
// speedup vs baseline: 1.0368x; 1.0368x over previous
#include <cuda_runtime.h>
#include <cuda_fp16.h>
#include <cstdint>

// Problem constants
#define N_ROWS   32768
#define D_DIM    512
#define C_BOOKS  64
#define K_CODES  16
#define M_OUT    128
#define NODES    15

// Scratch
__device__ __align__(16) uint32_t g_codes[N_ROWS * 8];               // 4-bit codes
__device__ __align__(16) __half   g_Lf16[M_OUT * C_BOOKS * K_CODES]; // L fp16 [m][1024]

// ---------------------------------------------------------------------------
// PTX helpers (sm_103 baseline — harness ptxas targets sm_103, no tcgen05)
// ---------------------------------------------------------------------------
__device__ __forceinline__ uint32_t smem_u32(const void* p) {
    uint32_t a;
    asm("{ .reg .u64 t; cvta.to.shared.u64 t, %1; cvt.u32.u64 %0, t; }" : "=r"(a) : "l"(p));
    return a;
}
__device__ __forceinline__ void cp16(uint32_t dst, const void* src) {
    asm volatile("cp.async.cg.shared.global [%0], [%1], 16;" :: "r"(dst), "l"(src) : "memory");
}
#define CP_COMMIT() asm volatile("cp.async.commit_group;" ::: "memory")
#define CP_WAIT(n)  asm volatile("cp.async.wait_group %0;" :: "n"(n) : "memory")

__device__ __forceinline__ void ldsm4(uint32_t& r0, uint32_t& r1, uint32_t& r2,
                                      uint32_t& r3, uint32_t addr) {
    asm volatile("ldmatrix.sync.aligned.m8n8.x4.shared.b16 {%0,%1,%2,%3}, [%4];"
                 : "=r"(r0), "=r"(r1), "=r"(r2), "=r"(r3) : "r"(addr));
}
__device__ __forceinline__ void mma16816(float* c, uint32_t a0, uint32_t a1,
                                         uint32_t a2, uint32_t a3,
                                         uint32_t b0, uint32_t b1) {
    asm volatile("mma.sync.aligned.m16n8k16.row.col.f32.f16.f16.f32 "
                 "{%0,%1,%2,%3}, {%4,%5,%6,%7}, {%8,%9}, {%0,%1,%2,%3};"
                 : "+f"(c[0]), "+f"(c[1]), "+f"(c[2]), "+f"(c[3])
                 : "r"(a0), "r"(a1), "r"(a2), "r"(a3), "r"(b0), "r"(b1));
}

// ---------------------------------------------------------------------------
// Kernel 1: encode (16 rows/CTA, 256 threads) + fused L->fp16 convert.
// ---------------------------------------------------------------------------
#define ENC_ROWS    16
#define ENC_THREADS 256
#define ROW_PAD     516

__global__ __launch_bounds__(ENC_THREADS)
void encode_kernel(const float* __restrict__ I,
                   const float* __restrict__ T,
                   const int*   __restrict__ dims,
                   const float* __restrict__ L)
{
    extern __shared__ float sm[];
    float* Ir = sm;
    float* Ts = sm + ENC_ROWS * ROW_PAD;
    int*   ds = (int*)(Ts + 960);

    const int tid = threadIdx.x;
    const int nb  = blockIdx.x * ENC_ROWS;
    const uint32_t sbase = smem_u32(sm);

    const char* src = (const char*)(I + (size_t)nb * D_DIM);
    #pragma unroll
    for (int i = 0; i < 8; i++) {
        int q = tid + ENC_THREADS * i;
        int r = q >> 7;
        int j = q & 127;
        cp16(sbase + (uint32_t)(r * (ROW_PAD * 4) + j * 16),
             src + (size_t)r * (D_DIM * 4) + j * 16);
    }
    CP_COMMIT();

    if (blockIdx.x < 128) {
        int q = blockIdx.x * 256 + tid;
        float4 v = ((const float4*)L)[q];
        ((__half2*)g_Lf16)[q * 2]     = __floats2half2_rn(v.x, v.y);
        ((__half2*)g_Lf16)[q * 2 + 1] = __floats2half2_rn(v.z, v.w);
    }

    for (int i = tid; i < 960; i += ENC_THREADS) Ts[i] = T[i];
    ds[tid] = dims[tid];

    CP_WAIT(0);
    __syncthreads();

    const int r  = tid >> 4;
    const int cg = tid & 15;
    const float* row = Ir + r * ROW_PAD;

    uint32_t pack = 0;
    #pragma unroll
    for (int j = 0; j < 4; j++) {
        const int c = cg * 4 + j;
        const int*   dp = ds + c * 4;
        const float* tp = Ts + c * NODES;
        const float v0 = row[dp[0]];
        const float v1 = row[dp[1]];
        const float v2 = row[dp[2]];
        const float v3 = row[dp[3]];
        int p;
        p = (v0 > tp[0]) ? 1 : 0;
        p = (p << 1) | ((v1 > tp[1 + p]) ? 1 : 0);
        p = (p << 1) | ((v2 > tp[3 + p]) ? 1 : 0);
        p = (p << 1) | ((v3 > tp[7 + p]) ? 1 : 0);
        pack |= ((uint32_t)p) << (4 * j);
    }
    ((uint16_t*)g_codes)[(size_t)(nb + r) * 16 + cg] = (uint16_t)pack;
}

// ---------------------------------------------------------------------------
// Kernel 2: tensor aggregation, barrier-free + SMEM A-LUT (r15 skeleton),
// with warp = 64n x 32m: each ldsm.x4 pair feeds 16 MMAs across 4 row-tiles,
// HALVING B smem traffic (64 -> 32 B per output element). acc[4][4][4]=64
// regs (fits thanks to LUT removing synthesis temporaries).
// CTA = 512n x 64m, 16 warps as 8(n) x 2(m). B + codes SMEM-resident,
// staged once via cp.async, ONE barrier. Grid (64,2) = 128 CTAs, one wave.
// ---------------------------------------------------------------------------
#define AGG_THREADS 512
#define NTILE       512
#define MTILE       64
#define BROW        2064                         // 2048B data + 16B pad per m-row
#define SM_CODES    0                            // 512 rows * 32B = 16384
#define SM_LUT      16384                        // 64 x uint2 = 512
#define SM_B        17408                        // 1024-aligned
#define SM_AGG      (SM_B + MTILE * BROW)        // 149504

__global__ __launch_bounds__(AGG_THREADS)
void agg_kernel(float* __restrict__ out)
{
    extern __shared__ __align__(16) char smem[];
    const uint32_t sb = smem_u32(smem);
    const int tid  = threadIdx.x;
    const int wid  = tid >> 5;
    const int lane = tid & 31;
    const int g    = lane >> 2;     // 0..7
    const int tg   = lane & 3;      // 0..3
    const int n0   = blockIdx.x * NTILE;
    const int mg0  = blockIdx.y * MTILE;

    // ---- stage codes: 512 rows * 32B ----
    {
        const char* srcc = (const char*)(g_codes + (size_t)n0 * 8);
        #pragma unroll
        for (int i = 0; i < 2; i++) {
            int q = tid + AGG_THREADS * i;
            cp16(sb + SM_CODES + (uint32_t)(q * 16), srcc + (size_t)q * 16);
        }
    }
    // ---- stage B: 64 m-rows x 128 x 16B ----
    {
        const char* srcL = (const char*)g_Lf16 + (size_t)mg0 * 2048;
        #pragma unroll
        for (int i = 0; i < 16; i++) {
            int q = tid + AGG_THREADS * i;
            int m = q >> 7, seg = q & 127;
            cp16(sb + SM_B + (uint32_t)(m * BROW + seg * 16),
                 srcL + (size_t)m * 2048 + seg * 16);
        }
    }
    CP_COMMIT();

    // ---- A-fragment LUT: entry[k][t] = {A_klow_slot, A_khigh_slot} ----
    if (tid < 64) {
        const uint32_t k  = (uint32_t)(tid >> 2);
        const uint32_t tt = (uint32_t)(tid & 3);
        const uint32_t hv = 0x3C00u << ((k & 1u) << 4);
        const uint32_t s  = k >> 1;
        uint2 e;
        e.x = (s == tt)      ? hv : 0u;
        e.y = (s == tt + 4u) ? hv : 0u;
        ((uint2*)(smem + SM_LUT))[tid] = e;
    }

    CP_WAIT(0);
    __syncthreads();            // the ONLY barrier

    const int t = lane >> 3;
    const uint32_t lane_off = (uint32_t)((((t >> 1) * 8) + (lane & 7)) * BROW
                                         + (t & 1) * 16);

    const int rbase = (wid >> 1) * 64;   // warp rows within CTA (64 each)
    const int mwarp = (wid & 1) * 32;    // warp m within CTA (32 each)
    const uint32_t* cs = (const uint32_t*)smem;
    const uint2* LUT = (const uint2*)(smem + SM_LUT);
    const uint32_t bwarp = sb + SM_B + (uint32_t)(mwarp * BROW) + lane_off;

    float acc[4][4][4];
    #pragma unroll
    for (int rt = 0; rt < 4; rt++)
        #pragma unroll
        for (int nb = 0; nb < 4; nb++)
            #pragma unroll
            for (int i = 0; i < 4; i++) acc[rt][nb][i] = 0.f;

    #pragma unroll 1
    for (int ch = 0; ch < 8; ch++) {
        const uint32_t bbase = bwarp + (uint32_t)(ch * 256);

        uint32_t wlo[4], whi[4];
        #pragma unroll
        for (int rt = 0; rt < 4; rt++) {
            wlo[rt] = cs[(rbase + 16 * rt + g)     * 8 + ch];
            whi[rt] = cs[(rbase + 16 * rt + g + 8) * 8 + ch];
        }

        #pragma unroll
        for (int kbl = 0; kbl < 8; kbl++) {
            // B fragments: 32 m = two 16-m ldmatrix.x4 (feeds 16 MMAs)
            uint32_t b[2][4];
            #pragma unroll
            for (int p = 0; p < 2; p++) {
                ldsm4(b[p][0], b[p][1], b[p][2], b[p][3],
                      bbase + (uint32_t)(kbl * 32) + (uint32_t)(p * 16 * BROW));
            }
            #pragma unroll
            for (int rt = 0; rt < 4; rt++) {
                const uint32_t klo = (wlo[rt] >> (4 * kbl)) & 15u;
                const uint32_t khi = (whi[rt] >> (4 * kbl)) & 15u;
                const uint2 elo = LUT[(int)(klo * 4) + tg];   // {A0, A2}
                const uint2 ehi = LUT[(int)(khi * 4) + tg];   // {A1, A3}
                #pragma unroll
                for (int p = 0; p < 2; p++) {
                    mma16816(acc[rt][2 * p],     elo.x, ehi.x, elo.y, ehi.y,
                             b[p][0], b[p][1]);
                    mma16816(acc[rt][2 * p + 1], elo.x, ehi.x, elo.y, ehi.y,
                             b[p][2], b[p][3]);
                }
            }
        }
    }

    // Epilogue: STG.64 pairs
    #pragma unroll
    for (int rt = 0; rt < 4; rt++) {
        const int rowA = n0 + rbase + 16 * rt + g;
        #pragma unroll
        for (int nb = 0; nb < 4; nb++) {
            float2 lo = make_float2(acc[rt][nb][0], acc[rt][nb][1]);
            float2 hi = make_float2(acc[rt][nb][2], acc[rt][nb][3]);
            *(float2*)(out + (size_t)rowA * M_OUT + mg0 + mwarp + nb * 8 + tg * 2)       = lo;
            *(float2*)(out + (size_t)(rowA + 8) * M_OUT + mg0 + mwarp + nb * 8 + tg * 2) = hi;
        }
    }
}

// ---------------------------------------------------------------------------
extern "C" void kernel_launch(void* const* d_in, const int* in_sizes, int n_in,
                              void* d_out, int out_size)
{
    (void)in_sizes; (void)n_in; (void)out_size;
    const float* I    = (const float*)d_in[0];
    const float* T    = (const float*)d_in[1];
    const float* L    = (const float*)d_in[2];
    const int*   dims = (const int*)d_in[5];
    float* out = (float*)d_out;

    const int encSmem = (ENC_ROWS * ROW_PAD + 960 + 256) * 4;  // 37888
    cudaFuncSetAttribute(encode_kernel, cudaFuncAttributeMaxDynamicSharedMemorySize, encSmem);
    cudaFuncSetAttribute(agg_kernel,    cudaFuncAttributeMaxDynamicSharedMemorySize, SM_AGG);

    encode_kernel<<<N_ROWS / ENC_ROWS, ENC_THREADS, encSmem>>>(I, T, dims, L);
    agg_kernel<<<dim3(N_ROWS / NTILE, M_OUT / MTILE), AGG_THREADS, SM_AGG>>>(out);
}